// round 1
// baseline (speedup 1.0000x reference)
#include <cuda_runtime.h>
#include <math.h>

// Problem constants
#define NPTS   2048
#define NNODES 8192
#define NCMP   1024
#define NWORDS 256           // NNODES / 32
#define CAP    192           // max candidates per row (T=2.2 -> mean ~114, sigma ~10.6; 7.4 sigma margin)
#define THRESH 2.2f

// Scratch: __device__ globals (no allocation allowed in kernel_launch)
__device__ unsigned int       g_bits[NCMP * NWORDS];     // [c][w] column bitsets, 1 MB
__device__ unsigned long long g_cand[(size_t)NPTS * CAP]; // packed {val:hi32, idx:lo32}, descending, 3 MB
__device__ int                g_cnt[NPTS];               // candidate count per row, -1 = overflow

// ---------------------------------------------------------------------------
// Kernel A: pack mask (int32 [N, C], row-major) into per-column bitsets.
// grid (256, 4), block 256. Block = one 32-row word w + one 256-column group.
// Each warp covers 32 columns; lane b reads mask[(w*32+b)][c]; ballot packs.
// ---------------------------------------------------------------------------
__global__ __launch_bounds__(256) void pack_bits_kernel(const int* __restrict__ mask) {
    int w    = blockIdx.x;                 // word index 0..255
    int cg   = blockIdx.y;                 // column group 0..3
    int warp = threadIdx.x >> 5;
    int lane = threadIdx.x & 31;
    int n    = w * 32 + lane;
    const int* row = mask + (size_t)n * NCMP;
    int cbase = cg * 256 + warp * 32;
    #pragma unroll 8
    for (int cc = 0; cc < 32; cc++) {
        int c = cbase + cc;
        unsigned int bal = __ballot_sync(0xFFFFFFFFu, row[c] != 0);
        if (lane == 0) g_bits[(size_t)c * NWORDS + w] = bal;
    }
}

// ---------------------------------------------------------------------------
// Kernel B: per-row candidate selection + descending rank sort.
// grid 2048, block 256. Compact all x[p,n] > THRESH, then O(nc^2) rank sort
// with (value, index) total order -> fully deterministic output.
// ---------------------------------------------------------------------------
__global__ __launch_bounds__(256) void select_cands_kernel(const float* __restrict__ x) {
    __shared__ float s_val[CAP];
    __shared__ int   s_idx[CAP];
    __shared__ int   s_cnt;

    int p   = blockIdx.x;
    int tid = threadIdx.x;
    if (tid == 0) s_cnt = 0;
    __syncthreads();

    const float* row = x + (size_t)p * NNODES;
    #pragma unroll
    for (int i = 0; i < NNODES / 256; i++) {
        int n = tid + 256 * i;             // coalesced
        float v = row[n];
        if (v > THRESH) {
            int pos = atomicAdd(&s_cnt, 1);
            if (pos < CAP) { s_val[pos] = v; s_idx[pos] = n; }
        }
    }
    __syncthreads();

    int nc = s_cnt;
    if (nc > CAP) {                        // overflow: force fallback for this row
        if (tid == 0) g_cnt[p] = -1;
        return;
    }
    if (tid == 0) g_cnt[p] = nc;

    if (tid < nc) {
        float v  = s_val[tid];
        int   id = s_idx[tid];
        int rank = 0;
        for (int j = 0; j < nc; j++) {
            float vj = s_val[j];
            rank += (vj > v) || (vj == v && s_idx[j] < id);
        }
        g_cand[(size_t)p * CAP + rank] =
            ((unsigned long long)__float_as_uint(v) << 32) | (unsigned int)id;
    }
}

// ---------------------------------------------------------------------------
// Kernel C: masked column max via descending-candidate early exit.
// Block = 32 columns x 256 rows. Column bitsets in shared, padded stride
// (NWORDS+1) so the warp-uniform word index maps to distinct banks per lane.
// Warp lanes = columns (fully coalesced 128B output per warp).
// Fallback (no candidate masked / overflow row) = exact bitset-driven scan;
// it also yields 0.0 for all-empty columns, matching the reference.
// ---------------------------------------------------------------------------
#define TC  32
#define TPR 256
#define SB_STRIDE (NWORDS + 1)

__global__ __launch_bounds__(256) void masked_colmax_kernel(const float* __restrict__ x,
                                                            float* __restrict__ out) {
    __shared__ unsigned int s_bits[TC * SB_STRIDE];  // ~32.1 KB

    int c0 = blockIdx.x * TC;
    int p0 = blockIdx.y * TPR;

    const unsigned int* src = g_bits + (size_t)c0 * NWORDS;
    for (int i = threadIdx.x; i < TC * NWORDS; i += blockDim.x) {
        int cl = i >> 8;                   // i / NWORDS
        int w  = i & (NWORDS - 1);
        s_bits[cl * SB_STRIDE + w] = src[i];
    }
    __syncthreads();

    int cl = threadIdx.x & 31;             // lane -> column
    int pr = threadIdx.x >> 5;             // warp -> row offset
    const unsigned int* mybits = s_bits + cl * SB_STRIDE;

    for (int p = p0 + pr; p < p0 + TPR; p += 8) {
        int cnt = g_cnt[p];                // warp-uniform broadcast
        float res = 0.0f;
        bool found = false;
        if (cnt >= 0) {
            const unsigned long long* cand = g_cand + (size_t)p * CAP;
            for (int k = 0; k < cnt; k++) {
                unsigned long long e = cand[k];   // warp-uniform address
                unsigned int idx = (unsigned int)e;
                if ((mybits[idx >> 5] >> (idx & 31u)) & 1u) {
                    res = __uint_as_float((unsigned int)(e >> 32));
                    found = true;
                    break;                 // first masked = exact masked max
                }
            }
        }
        if (!found) {
            float m = -INFINITY;
            const float* row = x + (size_t)p * NNODES;
            for (int w = 0; w < NWORDS; w++) {
                unsigned int b = mybits[w];
                while (b) {
                    int bit = __ffs(b) - 1;
                    m = fmaxf(m, row[w * 32 + bit]);
                    b &= b - 1;
                }
            }
            res = (m == -INFINITY) ? 0.0f : m;   // empty column -> 0.0
        }
        out[(size_t)p * NCMP + (c0 + cl)] = res;
    }
}

// ---------------------------------------------------------------------------
extern "C" void kernel_launch(void* const* d_in, const int* in_sizes, int n_in,
                              void* d_out, int out_size) {
    const float* x;
    const int*   mask;
    if (in_sizes[0] == NPTS * NNODES) {    // expected metadata order: x, learned_edge_states
        x    = (const float*)d_in[0];
        mask = (const int*)d_in[1];
    } else {                               // defensive swap
        x    = (const float*)d_in[1];
        mask = (const int*)d_in[0];
    }
    float* out = (float*)d_out;

    pack_bits_kernel<<<dim3(NWORDS, 4), 256>>>(mask);
    select_cands_kernel<<<NPTS, 256>>>(x);
    masked_colmax_kernel<<<dim3(NCMP / TC, NPTS / TPR), 256>>>(x, out);
}

// round 2
// speedup vs baseline: 1.5959x; 1.5959x over previous
#include <cuda_runtime.h>
#include <math.h>

// Problem constants
#define NPTS   2048
#define NNODES 8192
#define NCMP   1024
#define NWORDS 256           // NNODES / 32
#define CAP    192           // max candidates per row (T=2.2 -> mean ~114, sigma ~10.6)
#define THRESH 2.2f

// Scratch (__device__ globals; no allocation allowed)
// Layout: g_bits[w][c]  (w-major) -> coalesced writes in pack, coalesced tile loads in C.
__device__ unsigned int       g_bits[NWORDS * NCMP];      // 1 MB
__device__ unsigned long long g_cand[(size_t)NPTS * CAP]; // {val:hi32, idx:lo32}, descending; 3 MB
__device__ int                g_cnt[NPTS];                // candidate count per row, -1 = overflow

// ---------------------------------------------------------------------------
// Kernel A: pack mask (int32 [N, C] row-major) into w-major bitsets.
// Warp task = (word w, 128-column group). Lane owns 4 columns; builds 4 bit
// words from 32 coalesced int4 loads (each iteration = one 512B transaction).
// 2048 warp tasks -> 256 blocks x 8 warps.
// ---------------------------------------------------------------------------
__global__ __launch_bounds__(256) void pack_bits_kernel(const int* __restrict__ mask) {
    int warp = threadIdx.x >> 5;
    int lane = threadIdx.x & 31;
    int task = blockIdx.x * 8 + warp;      // 0..2047
    int w    = task >> 3;                  // 0..255
    int cg   = task & 7;                   // 0..7
    int c0   = cg * 128 + lane * 4;
    int n0   = w * 32;

    unsigned b0 = 0, b1 = 0, b2 = 0, b3 = 0;
    const int* base = mask + (size_t)n0 * NCMP + c0;
    #pragma unroll 8
    for (int i = 0; i < 32; i++) {
        int4 v = *(const int4*)(base + (size_t)i * NCMP);
        b0 |= (unsigned)(v.x != 0) << i;
        b1 |= (unsigned)(v.y != 0) << i;
        b2 |= (unsigned)(v.z != 0) << i;
        b3 |= (unsigned)(v.w != 0) << i;
    }
    uint4 o; o.x = b0; o.y = b1; o.z = b2; o.w = b3;
    *(uint4*)(g_bits + (size_t)w * NCMP + c0) = o;       // coalesced 512B
}

// ---------------------------------------------------------------------------
// Kernel B: per-row candidate selection + descending rank sort (deterministic
// via (value, index) total order). float4 loads on the 64MB stream.
// ---------------------------------------------------------------------------
__global__ __launch_bounds__(256) void select_cands_kernel(const float* __restrict__ x) {
    __shared__ float s_val[CAP];
    __shared__ int   s_idx[CAP];
    __shared__ int   s_cnt;

    int p   = blockIdx.x;
    int tid = threadIdx.x;
    if (tid == 0) s_cnt = 0;
    __syncthreads();

    const float4* row4 = (const float4*)(x + (size_t)p * NNODES);
    #pragma unroll
    for (int i = 0; i < NNODES / (256 * 4); i++) {       // 8 iterations
        int q = tid + 256 * i;                           // coalesced float4
        float4 v = row4[q];
        int n = q * 4;
        if (v.x > THRESH) { int pos = atomicAdd(&s_cnt, 1); if (pos < CAP) { s_val[pos] = v.x; s_idx[pos] = n;     } }
        if (v.y > THRESH) { int pos = atomicAdd(&s_cnt, 1); if (pos < CAP) { s_val[pos] = v.y; s_idx[pos] = n + 1; } }
        if (v.z > THRESH) { int pos = atomicAdd(&s_cnt, 1); if (pos < CAP) { s_val[pos] = v.z; s_idx[pos] = n + 2; } }
        if (v.w > THRESH) { int pos = atomicAdd(&s_cnt, 1); if (pos < CAP) { s_val[pos] = v.w; s_idx[pos] = n + 3; } }
    }
    __syncthreads();

    int nc = s_cnt;
    if (nc > CAP) {                                      // overflow -> exact fallback in C
        if (tid == 0) g_cnt[p] = -1;
        return;
    }
    if (tid == 0) g_cnt[p] = nc;

    if (tid < nc) {
        float v  = s_val[tid];
        int   id = s_idx[tid];
        int rank = 0;
        for (int j = 0; j < nc; j++) {
            float vj = s_val[j];
            rank += (vj > v) || (vj == v && s_idx[j] < id);
        }
        g_cand[(size_t)p * CAP + rank] =
            ((unsigned long long)__float_as_uint(v) << 32) | (unsigned int)id;
    }
}

// ---------------------------------------------------------------------------
// Kernel C: masked column max via descending-candidate early exit.
// Block = 32 columns x 128 rows. Bitset tile in shared, w-major stride 32:
// candidate idx is warp-uniform -> lanes hit 32 consecutive words = 32 banks,
// conflict-free with zero padding. Candidate list read 2-at-a-time (16B
// warp-uniform loads) to halve the serial latency chain.
// ---------------------------------------------------------------------------
#define TC  32
#define TPR 128

__global__ __launch_bounds__(256) void masked_colmax_kernel(const float* __restrict__ x,
                                                            float* __restrict__ out) {
    __shared__ unsigned int s_bits[NWORDS * TC];         // 32 KB, [w][cl]

    int c0 = blockIdx.x * TC;
    int p0 = blockIdx.y * TPR;

    // Coalesced tile load: 2048 uint4 across 256 threads (8 passes).
    for (int i = threadIdx.x; i < NWORDS * (TC / 4); i += 256) {
        int w  = i >> 3;
        int cq = (i & 7) * 4;
        uint4 v = *(const uint4*)(g_bits + (size_t)w * NCMP + c0 + cq);
        *(uint4*)(s_bits + w * TC + cq) = v;
    }
    __syncthreads();

    int cl = threadIdx.x & 31;             // lane -> column
    int pr = threadIdx.x >> 5;             // warp -> row offset

    for (int p = p0 + pr; p < p0 + TPR; p += 8) {
        int cnt = g_cnt[p];                // warp-uniform
        float res = 0.0f;
        bool found = false;
        if (cnt >= 0) {
            const ulonglong2* cand2 = (const ulonglong2*)(g_cand + (size_t)p * CAP);
            int npairs = (cnt + 1) >> 1;
            for (int k = 0; k < npairs && !found; k++) {
                ulonglong2 e = cand2[k];                 // warp-uniform 16B load
                unsigned int i0 = (unsigned int)e.x;
                if ((s_bits[(i0 >> 5) * TC + cl] >> (i0 & 31u)) & 1u) {
                    res = __uint_as_float((unsigned int)(e.x >> 32));
                    found = true;
                } else if (2 * k + 1 < cnt) {
                    unsigned int i1 = (unsigned int)e.y;
                    if ((s_bits[(i1 >> 5) * TC + cl] >> (i1 & 31u)) & 1u) {
                        res = __uint_as_float((unsigned int)(e.y >> 32));
                        found = true;
                    }
                }
            }
        }
        if (!found) {
            // Exact fallback: bitset-driven scan of the row (also handles
            // empty columns -> 0.0, matching the reference).
            float m = -INFINITY;
            const float* row = x + (size_t)p * NNODES;
            for (int w = 0; w < NWORDS; w++) {
                unsigned int b = s_bits[w * TC + cl];
                while (b) {
                    int bit = __ffs(b) - 1;
                    m = fmaxf(m, row[w * 32 + bit]);
                    b &= b - 1;
                }
            }
            res = (m == -INFINITY) ? 0.0f : m;
        }
        out[(size_t)p * NCMP + (c0 + cl)] = res;
    }
}

// ---------------------------------------------------------------------------
extern "C" void kernel_launch(void* const* d_in, const int* in_sizes, int n_in,
                              void* d_out, int out_size) {
    const float* x;
    const int*   mask;
    if (in_sizes[0] == NPTS * NNODES) {    // metadata order: x, learned_edge_states
        x    = (const float*)d_in[0];
        mask = (const int*)d_in[1];
    } else {
        x    = (const float*)d_in[1];
        mask = (const int*)d_in[0];
    }
    float* out = (float*)d_out;

    pack_bits_kernel<<<256, 256>>>(mask);
    select_cands_kernel<<<NPTS, 256>>>(x);
    masked_colmax_kernel<<<dim3(NCMP / TC, NPTS / TPR), 256>>>(x, out);
}

// round 4
// speedup vs baseline: 1.6261x; 1.0190x over previous
#include <cuda_runtime.h>
#include <math.h>

// Problem constants
#define NPTS   2048
#define NNODES 8192
#define NCMP   1024
#define NWORDS 256           // NNODES / 32
#define CAP    192           // candidates/row (T=2.2 -> mean ~114, sigma ~10.6)
#define THRESH 2.2f

// Scratch (__device__ globals). g_bits is w-major: g_bits[w][c].
__device__ unsigned int       g_bits[NWORDS * NCMP];      // 1 MB
__device__ unsigned long long g_cand[(size_t)NPTS * CAP]; // {val:hi32, idx:lo32}, descending; 3 MB
__device__ int                g_cnt[NPTS];                // count per row, -1 = overflow

// ---------------------------------------------------------------------------
// Kernel A: pack mask (int32 [N, C] row-major) into w-major bitsets.
// Warp task = (word w, 64-column group). Lane owns 2 columns (int2 loads,
// fully coalesced). 4096 warp tasks -> 512 blocks x 8 warps (2x occupancy).
// ---------------------------------------------------------------------------
__global__ __launch_bounds__(256) void pack_bits_kernel(const int* __restrict__ mask) {
    int warp = threadIdx.x >> 5;
    int lane = threadIdx.x & 31;
    int task = blockIdx.x * 8 + warp;      // 0..4095
    int w    = task >> 4;                  // 0..255
    int cg   = task & 15;                  // 0..15
    int c0   = cg * 64 + lane * 2;
    int n0   = w * 32;

    unsigned b0 = 0, b1 = 0;
    const int* base = mask + (size_t)n0 * NCMP + c0;
    #pragma unroll
    for (int i = 0; i < 32; i++) {
        int2 v = *(const int2*)(base + (size_t)i * NCMP);
        b0 |= (unsigned)(v.x != 0) << i;
        b1 |= (unsigned)(v.y != 0) << i;
    }
    uint2 o; o.x = b0; o.y = b1;
    *(uint2*)(g_bits + (size_t)w * NCMP + c0) = o;       // coalesced 256B/warp
}

// ---------------------------------------------------------------------------
// Kernel B: per-row candidate selection (ballot-aggregated compaction: one
// shared atomic per warp per float4 pass) + O(nc^2) descending rank sort with
// (value, index) total order -> deterministic final layout.
// ---------------------------------------------------------------------------
__global__ __launch_bounds__(256) void select_cands_kernel(const float* __restrict__ x) {
    __shared__ float s_val[CAP];
    __shared__ int   s_idx[CAP];
    __shared__ int   s_cnt;

    int p    = blockIdx.x;
    int tid  = threadIdx.x;
    int lane = tid & 31;
    unsigned lt = (1u << lane) - 1u;
    if (tid == 0) s_cnt = 0;
    __syncthreads();

    const float4* row4 = (const float4*)(x + (size_t)p * NNODES);
    #pragma unroll
    for (int i = 0; i < NNODES / (256 * 4); i++) {       // 8 passes
        int q = tid + 256 * i;
        float4 v = row4[q];
        int n = q * 4;
        unsigned m0 = __ballot_sync(0xFFFFFFFFu, v.x > THRESH);
        unsigned m1 = __ballot_sync(0xFFFFFFFFu, v.y > THRESH);
        unsigned m2 = __ballot_sync(0xFFFFFFFFu, v.z > THRESH);
        unsigned m3 = __ballot_sync(0xFFFFFFFFu, v.w > THRESH);
        int tot = __popc(m0) + __popc(m1) + __popc(m2) + __popc(m3);
        int wbase = 0;
        if (lane == 0 && tot) wbase = atomicAdd(&s_cnt, tot);
        wbase = __shfl_sync(0xFFFFFFFFu, wbase, 0);
        int off = wbase;
        if (v.x > THRESH) { int pos = off + __popc(m0 & lt); if (pos < CAP) { s_val[pos] = v.x; s_idx[pos] = n;     } }
        off += __popc(m0);
        if (v.y > THRESH) { int pos = off + __popc(m1 & lt); if (pos < CAP) { s_val[pos] = v.y; s_idx[pos] = n + 1; } }
        off += __popc(m1);
        if (v.z > THRESH) { int pos = off + __popc(m2 & lt); if (pos < CAP) { s_val[pos] = v.z; s_idx[pos] = n + 2; } }
        off += __popc(m2);
        if (v.w > THRESH) { int pos = off + __popc(m3 & lt); if (pos < CAP) { s_val[pos] = v.w; s_idx[pos] = n + 3; } }
    }
    __syncthreads();

    int nc = s_cnt;
    if (nc > CAP) {                                      // overflow -> exact fallback in C
        if (tid == 0) g_cnt[p] = -1;
        return;
    }
    if (tid == 0) g_cnt[p] = nc;

    if (tid < nc) {
        float v  = s_val[tid];
        int   id = s_idx[tid];
        int rank = 0;
        for (int j = 0; j < nc; j++) {
            float vj = s_val[j];
            rank += (vj > v) || (vj == v && s_idx[j] < id);
        }
        g_cand[(size_t)p * CAP + rank] =
            ((unsigned long long)__float_as_uint(v) << 32) | (unsigned int)id;
    }
}

// ---------------------------------------------------------------------------
// Kernel C: masked column max, batched candidate probe (8 at a time via 4
// independent 16B warp-uniform loads -> one load latency per row typically).
// Block = 32 columns x 128 rows; bitset tile [w][cl] in shared (bank-clean).
// ---------------------------------------------------------------------------
#define TC  32
#define TPR 128

__global__ __launch_bounds__(256) void masked_colmax_kernel(const float* __restrict__ x,
                                                            float* __restrict__ out) {
    __shared__ unsigned int s_bits[NWORDS * TC];         // 32 KB

    int c0 = blockIdx.x * TC;
    int p0 = blockIdx.y * TPR;

    for (int i = threadIdx.x; i < NWORDS * (TC / 4); i += 256) {
        int w  = i >> 3;
        int cq = (i & 7) * 4;
        *(uint4*)(s_bits + w * TC + cq) =
            *(const uint4*)(g_bits + (size_t)w * NCMP + c0 + cq);
    }
    __syncthreads();

    int cl = threadIdx.x & 31;
    int pr = threadIdx.x >> 5;

    for (int p = p0 + pr; p < p0 + TPR; p += 8) {
        int cnt = g_cnt[p];                              // warp-uniform
        float res = 0.0f;
        bool found = false;
        if (cnt >= 0) {
            const ulonglong2* cand2 = (const ulonglong2*)(g_cand + (size_t)p * CAP);
            #pragma unroll 1
            for (int base = 0; base < cnt && !found; base += 8) {
                int b2 = base >> 1;                      // 4 independent 16B loads
                ulonglong2 e0 = cand2[b2 + 0];
                ulonglong2 e1 = cand2[b2 + 1];
                ulonglong2 e2 = cand2[b2 + 2];
                ulonglong2 e3 = cand2[b2 + 3];
                #define HIT(e, j, hv, vv)                                         \
                    unsigned idx##j = (unsigned)(e);                              \
                    float vv = __uint_as_float((unsigned)((e) >> 32));            \
                    bool hv = (base + j < cnt) &&                                 \
                        ((s_bits[(idx##j >> 5) * TC + cl] >> (idx##j & 31u)) & 1u);
                HIT(e0.x, 0, h0, v0) HIT(e0.y, 1, h1, v1)
                HIT(e1.x, 2, h2, v2) HIT(e1.y, 3, h3, v3)
                HIT(e2.x, 4, h4, v4) HIT(e2.y, 5, h5, v5)
                HIT(e3.x, 6, h6, v6) HIT(e3.y, 7, h7, v7)
                #undef HIT
                // first hit (smallest j) wins: assign in descending j order
                if (h7) res = v7; if (h6) res = v6; if (h5) res = v5; if (h4) res = v4;
                if (h3) res = v3; if (h2) res = v2; if (h1) res = v1; if (h0) res = v0;
                found = h0 | h1 | h2 | h3 | h4 | h5 | h6 | h7;
            }
        }
        if (!found) {
            // Exact fallback (overflow rows / no candidate masked / empty col).
            float m = -INFINITY;
            const float* row = x + (size_t)p * NNODES;
            for (int w = 0; w < NWORDS; w++) {
                unsigned int b = s_bits[w * TC + cl];
                while (b) {
                    int bit = __ffs(b) - 1;
                    m = fmaxf(m, row[w * 32 + bit]);
                    b &= b - 1;
                }
            }
            res = (m == -INFINITY) ? 0.0f : m;           // empty column -> 0.0
        }
        out[(size_t)p * NCMP + (c0 + cl)] = res;
    }
}

// ---------------------------------------------------------------------------
extern "C" void kernel_launch(void* const* d_in, const int* in_sizes, int n_in,
                              void* d_out, int out_size) {
    const float* x;
    const int*   mask;
    if (in_sizes[0] == NPTS * NNODES) {    // metadata order: x, learned_edge_states
        x    = (const float*)d_in[0];
        mask = (const int*)d_in[1];
    } else {
        x    = (const float*)d_in[1];
        mask = (const int*)d_in[0];
    }
    float* out = (float*)d_out;

    pack_bits_kernel<<<512, 256>>>(mask);
    select_cands_kernel<<<NPTS, 256>>>(x);
    masked_colmax_kernel<<<dim3(NCMP / TC, NPTS / TPR), 256>>>(x, out);
}